// round 6
// baseline (speedup 1.0000x reference)
#include <cuda_runtime.h>
#include <cstddef>
#include <cstdint>

// Layout constants
#define DS    36           // item row stride (floats): cols 0-31 matrix, 32 bias, 33-35 pad
#define WS    33           // staged-W row stride (floats): conflict-free scalar LDS
#define NBLK  592          // 4 blocks/SM on 148+ SMs (all resident — required for grid barrier)
#define NTHR  64           // 2 warps: warp w owns output cols [16w, 16w+16)
#define L1B   74           // 592/8
#define L2B   10           // ceil(74/8)

// Scratch (allocation-free: __device__ globals), 16B-aligned for float4 access
__device__ __align__(16) float g_it0[NBLK * 32 * DS];
__device__ __align__(16) float g_it1[L1B * 32 * DS];
__device__ __align__(16) float g_it2[L2B * 32 * DS];
__device__ __align__(16) float g_fin[32 * DS];
__device__ __align__(16) float g_P[2048 * 32];
__device__ int          g_flag;
__device__ unsigned int bar_count;   // zero-init
__device__ unsigned int bar_gen;     // monotonic across graph replays

typedef unsigned long long u64;

__device__ __forceinline__ u64 pack2(float x) {
    u64 r; unsigned int xi = __float_as_uint(x);
    asm("mov.b64 %0, {%1, %1};" : "=l"(r) : "r"(xi));
    return r;
}
// d.lo += a.lo*b.lo ; d.hi += a.hi*b.hi  (one FMA-pipe slot, 2 MACs)
__device__ __forceinline__ void fma2(u64& d, u64 a, u64 b) {
    asm("fma.rn.f32x2 %0, %1, %2, %0;" : "+l"(d) : "l"(a), "l"(b));
}

// Epoch-based grid-wide barrier. Requires all gridDim.x blocks resident.
__device__ __forceinline__ void grid_sync() {
    __threadfence();
    __syncthreads();
    if (threadIdx.x == 0) {
        unsigned int gen = *(volatile unsigned int*)&bar_gen;
        if (atomicAdd(&bar_count, 1u) == gridDim.x - 1u) {
            bar_count = 0u;
            __threadfence();
            *(volatile unsigned int*)&bar_gen = gen + 1u;
        } else {
            while (*(volatile unsigned int*)&bar_gen == gen) __nanosleep(64);
        }
    }
    __syncthreads();
    __threadfence();
}

// One affine composition step.
//   Uo[l][j]  = sum_k Wrow_l[k] * U[k][j]       (j in [16w, 16w+16))
//   Uo[l][32] = sum_k Wrow_l[k] * U[k][32] + bl (warp 1 only)
// lane l = row; W rows from stride-33 shared (conflict-free scalar LDS);
// U rows read as broadcast LDS.128 (uniform address across the warp).
__device__ __forceinline__ void affine_core(
    const float (*U)[DS], const float* __restrict__ sWmat, float bl,
    float (*Uo)[DS], int lane, int w)
{
    const float* wr_s = sWmat + lane * WS;
    float wr[32];
#pragma unroll
    for (int k = 0; k < 32; ++k) wr[k] = wr_s[k];

    const int j0 = w * 16;
    u64 a0 = 0, a1 = 0, a2 = 0, a3 = 0, a4 = 0, a5 = 0, a6 = 0, a7 = 0;
    float accb = bl;
#pragma unroll
    for (int k = 0; k < 32; ++k) {
        u64 wk = pack2(wr[k]);
        const ulonglong2* up = (const ulonglong2*)&U[k][j0];
        ulonglong2 u01 = up[0];
        ulonglong2 u23 = up[1];
        fma2(a0, wk, u01.x); fma2(a1, wk, u01.y);
        fma2(a2, wk, u23.x); fma2(a3, wk, u23.y);
        ulonglong2 u45 = up[2];
        ulonglong2 u67 = up[3];
        fma2(a4, wk, u45.x); fma2(a5, wk, u45.y);
        fma2(a6, wk, u67.x); fma2(a7, wk, u67.y);
        if (w == 1) accb = fmaf(wr[k], U[k][32], accb);
    }
    ulonglong2* op = (ulonglong2*)&Uo[lane][j0];
    ulonglong2 r;
    r.x = a0; r.y = a1; op[0] = r;
    r.x = a2; r.y = a3; op[1] = r;
    r.x = a4; r.y = a5; op[2] = r;
    r.x = a6; r.y = a7; op[3] = r;
    if (w == 1) Uo[lane][32] = accb;
}

// Stage 16 prefetched floats into stride-33 shared W.
// Thread t holds matrix floats [t*16, t*16+16): row c = t>>1, col base (t&1)*16.
__device__ __forceinline__ void stage_W(float* sWmat, const float4* f, int t) {
    const int c  = t >> 1;
    const int jb = (t & 1) * 16;
    float* dst = sWmat + c * WS + jb;
#pragma unroll
    for (int q = 0; q < 4; ++q) {
        dst[q * 4 + 0] = f[q].x; dst[q * 4 + 1] = f[q].y;
        dst[q * 4 + 2] = f[q].z; dst[q * 4 + 3] = f[q].w;
    }
}

// Sequentially compose n items in[startItem .. startItem+n) -> out (one item).
__device__ void combine_seq(const float* __restrict__ in, float* __restrict__ out,
                            int startItem, int n,
                            float sU[2][32][DS], float sW[2][32 * WS],
                            int t, int lane, int w)
{
    const float* first = in + (size_t)startItem * (32 * DS);
    for (int idx = t; idx < 32 * DS; idx += NTHR)
        (&sU[0][0][0])[idx] = first[idx];

    float4 f[4];
    float breg = 0.f;
    if (n > 1) {
        const float* it = in + (size_t)(startItem + 1) * (32 * DS);
        const float* rp = it + (t >> 1) * DS + (t & 1) * 16;
#pragma unroll
        for (int q = 0; q < 4; ++q) f[q] = *(const float4*)(rp + q * 4);
        if (w == 1) breg = it[lane * DS + 32];
    }

    int p = 0;
    for (int q = 1; q < n; ++q, p ^= 1) {
        stage_W(sW[p], f, t);
        float bl = breg;
        __syncthreads();
        if (q + 1 < n) {
            const float* it = in + (size_t)(startItem + q + 1) * (32 * DS);
            const float* rp = it + (t >> 1) * DS + (t & 1) * 16;
#pragma unroll
            for (int qq = 0; qq < 4; ++qq) f[qq] = *(const float4*)(rp + qq * 4);
            if (w == 1) breg = it[lane * DS + 32];
        }
        affine_core(sU[p], sW[p], bl, sU[p ^ 1], lane, w);
    }
    __syncthreads();
    const float* srcU = &sU[p][0][0];
    for (int idx = t; idx < 32 * DS; idx += NTHR)
        out[idx] = srcU[idx];
}

__global__ __launch_bounds__(NTHR, 4) void k_all(
    const float* __restrict__ W, const float* __restrict__ b,
    const float* __restrict__ y, const float* __restrict__ z,
    const float* __restrict__ x, float* __restrict__ out)
{
    __shared__ float sU[2][32][DS];
    __shared__ float sW[2][32 * WS];
    __shared__ float shv[32];
    __shared__ int   sflag;

    const int t    = threadIdx.x;
    const int lane = t & 31;
    const int w    = t >> 5;
    const int blk  = blockIdx.x;

    // ---- Phase A: per-block chunk of layers (10000 = 528*17 + 64*16) ----
    {
        const int start = blk * 16 + (blk < 528 ? blk : 528);
        const int end   = start + 16 + (blk < 528 ? 1 : 0);

        for (int idx = t; idx < 32 * DS; idx += NTHR) {
            int r = idx / DS, q = idx % DS;
            sU[0][r][q] = (q == r) ? 1.0f : 0.0f;
        }

        float4 f[4];
        {
            const float4* src = (const float4*)(W + (size_t)start * 1024 + t * 16);
#pragma unroll
            for (int q = 0; q < 4; ++q) f[q] = src[q];
        }
        float breg = (w == 1) ? b[start * 32 + lane] : 0.f;

        int p = 0;
        for (int i = start; i < end; ++i, p ^= 1) {
            stage_W(sW[p], f, t);
            float bl = breg;
            __syncthreads();
            if (i + 1 < end) {
                const float4* src = (const float4*)(W + (size_t)(i + 1) * 1024 + t * 16);
#pragma unroll
                for (int q = 0; q < 4; ++q) f[q] = src[q];
                if (w == 1) breg = b[(i + 1) * 32 + lane];
            }
            affine_core(sU[p], sW[p], bl, sU[p ^ 1], lane, w);
        }
        __syncthreads();
        float* dst = g_it0 + (size_t)blk * (32 * DS);
        const float* srcU = &sU[p][0][0];
        for (int idx = t; idx < 32 * DS; idx += NTHR)
            dst[idx] = srcU[idx];
    }
    grid_sync();

    // ---- Tree level 1: 592 -> 74 ----
    if (blk < L1B)
        combine_seq(g_it0, g_it1 + (size_t)blk * (32 * DS), blk * 8, 8, sU, sW, t, lane, w);
    if (blk == L1B && t == 0) g_flag = 0;   // reset flag for this run (pre-P barrier)
    grid_sync();

    // ---- Tree level 2: 74 -> 10 ----
    if (blk < L2B)
        combine_seq(g_it1, g_it2 + (size_t)blk * (32 * DS), blk * 8,
                    min(8, L1B - blk * 8), sU, sW, t, lane, w);
    grid_sync();

    // ---- Tree level 3: 10 -> 1 ----
    if (blk == 0)
        combine_seq(g_it2, g_fin, 0, L2B, sU, sW, t, lane, w);
    grid_sync();

    // ---- Phase P: P = (y+z) @ M, M[k][d] = U[d][k]; flag if any nonzero ----
    {
        float* shU = &sW[0][0];   // reuse: 32*DS = 1152 floats fits in sW (2112)
        for (int idx = t; idx < 32 * DS; idx += NTHR) shU[idx] = g_fin[idx];
        __syncthreads();
        const int nth = NBLK * NTHR;
        int any = 0;
        for (int gid = blk * NTHR + t; gid < 2048 * 32; gid += nth) {
            const int e = gid >> 5, d = gid & 31;
            const float* yr = y + e * 32;
            const float* zr = z + e * 32;
            float acc = 0.f;
#pragma unroll
            for (int m = 0; m < 32; ++m)
                acc = fmaf(yr[m] + zr[m], shU[d * DS + m], acc);
            g_P[gid] = acc;
            if (acc != 0.0f) any = 1;
        }
        if (any) atomicOr(&g_flag, 1);
    }
    grid_sync();

    // ---- Phase OUT ----
    {
        if (t < 32) shv[t] = g_fin[t * DS + 32];
        if (t == 0) sflag = g_flag;
        __syncthreads();
        const int nth = NBLK * NTHR;
        if (!sflag) {
            // P == 0 exactly: out[row][d] = v[d] (bit-equal to full path)
            for (int gid = blk * NTHR + t; gid < 1024 * 32; gid += nth)
                out[gid] = shv[gid & 31];
        } else {
            for (int gid = blk * NTHR + t; gid < 1024 * 32; gid += nth) {
                const int row = gid >> 5, d = gid & 31;
                const float* xr = x + (size_t)row * 2048;
                float acc = shv[d];
#pragma unroll 4
                for (int m = 0; m < 2048; m += 4) {
                    float4 xv = *(const float4*)(xr + m);
                    acc = fmaf(xv.x, g_P[(m + 0) * 32 + d], acc);
                    acc = fmaf(xv.y, g_P[(m + 1) * 32 + d], acc);
                    acc = fmaf(xv.z, g_P[(m + 2) * 32 + d], acc);
                    acc = fmaf(xv.w, g_P[(m + 3) * 32 + d], acc);
                }
                out[gid] = acc;
            }
        }
    }
}

extern "C" void kernel_launch(void* const* d_in, const int* in_sizes, int n_in,
                              void* d_out, int out_size)
{
    // Bind inputs by element count:
    //  x: 1024*2048, y/z: 65536 (symmetric: only y+z used),
    //  W: 10000*32*32, b: 10000*32
    const float *x = nullptr, *y = nullptr, *z = nullptr, *W = nullptr, *b = nullptr;
    for (int i = 0; i < n_in; ++i) {
        const float* p = (const float*)d_in[i];
        switch (in_sizes[i]) {
            case 2097152:  x = p; break;
            case 10240000: W = p; break;
            case 320000:   b = p; break;
            case 65536:    if (!y) y = p; else z = p; break;
            default: break;
        }
    }
    float* out = (float*)d_out;

    k_all<<<NBLK, NTHR>>>(W, b, y, z, x, out);
}